// round 8
// baseline (speedup 1.0000x reference)
#include <cuda_runtime.h>
#include <cuda_fp16.h>
#include <cstdint>

#define Nn   20000
#define Ee   320000
#define XDIM 128
#define Hh   256
#define LL   4
#define GG   128
#define CC   10
#define EPSF 1e-5f

// weight tile images: 72 global ktiles (enc 8 + 4x16 conv), 4 col-blocks each,
// tile = [64 n][16 k] halves = 1024 halves = 2KB, swizzled for ldmatrix
#define NKT   (8 + LL * 16)          // 72
#define NTILE (NKT * 4)              // 288

// ---------------- scratch ----------------
__device__ float g_h [Nn * Hh];
__device__ float g_t [Nn * Hh];
__device__ float g_t2[Nn * Hh];
__device__ __align__(16) unsigned short g_Wh16[NTILE * 1024];
__device__ __align__(16) unsigned short g_Wl16[NTILE * 1024];
__device__ float g_dinv[Nn];
__device__ int   g_deg[Nn];
__device__ int   g_rowptr[Nn + 1];
__device__ int   g_cursor[Nn];
__device__ int   g_csrc[Ee];
__device__ float g_cw[Ee];
__device__ float g_colsum[Hh];
__device__ float g_colsq[Hh];
__device__ float g_scale[Hh];
__device__ float g_shift[Hh];
__device__ float g_gsum[GG * Hh];
__device__ int   g_gcnt[GG];
__device__ float g_m1[GG * Hh];
__device__ float g_m2[GG * Hh];

// swizzled byte offset within a [rows][16k] half tile (32B rows)
__host__ __device__ __forceinline__ uint32_t tswz(int row, int k8) {
    return (uint32_t)(row * 32 + ((k8 ^ ((row >> 2) & 1)) << 4));
}

__device__ __forceinline__ uint32_t smem_u32(const void* p) {
    uint32_t a;
    asm("{ .reg .u64 t; cvta.to.shared.u64 t, %1; cvt.u32.u64 %0, t; }" : "=r"(a) : "l"(p));
    return a;
}

__device__ __forceinline__ void mma_f16(float4& d,
    uint32_t a0, uint32_t a1, uint32_t a2, uint32_t a3, uint32_t b0, uint32_t b1)
{
    asm volatile(
        "mma.sync.aligned.m16n8k16.row.col.f32.f16.f16.f32 "
        "{%0,%1,%2,%3}, {%4,%5,%6,%7}, {%8,%9}, {%0,%1,%2,%3};\n"
        : "+f"(d.x), "+f"(d.y), "+f"(d.z), "+f"(d.w)
        : "r"(a0), "r"(a1), "r"(a2), "r"(a3), "r"(b0), "r"(b1));
}

#define LDSM4(r, addr)                                                           \
    asm volatile("ldmatrix.sync.aligned.m8n8.x4.shared.b16 {%0,%1,%2,%3}, [%4];" \
        : "=r"((r)[0]), "=r"((r)[1]), "=r"((r)[2]), "=r"((r)[3]) : "r"(addr))

#define CPASYNC16(sa, ga) \
    asm volatile("cp.async.cg.shared.global [%0], [%1], 16;" :: "r"(sa), "l"(ga))
#define CPCOMMIT() asm volatile("cp.async.commit_group;" ::: "memory")
#define CPWAIT0()  asm volatile("cp.async.wait_group 0;" ::: "memory")

// ---------------- setup ----------------
__global__ void zero_k() {
    int i = blockIdx.x * blockDim.x + threadIdx.x;
    if (i < Nn)      g_deg[i]  = 0;
    if (i < GG * Hh) g_gsum[i] = 0.f;
    if (i < GG)      g_gcnt[i] = 0;
    if (i < Hh)      { g_colsum[i] = 0.f; g_colsq[i] = 0.f; }
}

// split weights into fp16 hi/lo tile images: tix = globalKtile*4 + colblock
__global__ void prep_k(const float* __restrict__ encW, const float* __restrict__ convW) {
    int i = blockIdx.x * blockDim.x + threadIdx.x;
    if (i >= (XDIM + LL * Hh) * Hh) return;
    int kglobal = i >> 8;         // 0..1151
    int n       = i & 255;
    float val;
    if (kglobal < XDIM) {
        val = encW[kglobal * Hh + n];
    } else {
        int kg2 = kglobal - XDIM;
        val = convW[(size_t)(kg2 >> 8) * Hh * Hh + (kg2 & 255) * Hh + n];
    }
    __half h = __float2half_rn(val);
    __half l = __float2half_rn(val - __half2float(h));
    int tix  = (kglobal >> 4) * 4 + (n >> 6);
    int row  = n & 63;
    int kk   = kglobal & 15;
    uint32_t off = tswz(row, kk >> 3) + (kk & 7) * 2;   // bytes
    g_Wh16[tix * 1024 + (off >> 1)] = __half_as_ushort(h);
    g_Wl16[tix * 1024 + (off >> 1)] = __half_as_ushort(l);
}

__global__ void degree_k(const int* __restrict__ dst, const int* __restrict__ batch) {
    int i = blockIdx.x * blockDim.x + threadIdx.x;
    if (i < Ee) atomicAdd(&g_deg[dst[i]], 1);
    if (i < Nn) atomicAdd(&g_gcnt[batch[i]], 1);
}

__global__ void scan_k() {
    __shared__ int wsum[32];
    const int CH = 20;
    int tid = threadIdx.x, lane = tid & 31, wid = tid >> 5;
    int base = tid * CH;
    int dv[CH];
    int s = 0;
    if (base < Nn) {
        const int4* dp = (const int4*)(g_deg + base);
#pragma unroll
        for (int q = 0; q < 5; q++) {
            int4 t = dp[q];
            dv[q * 4 + 0] = t.x; dv[q * 4 + 1] = t.y;
            dv[q * 4 + 2] = t.z; dv[q * 4 + 3] = t.w;
        }
#pragma unroll
        for (int c = 0; c < CH; c++) s += dv[c];
    }
    int inc = s;
#pragma unroll
    for (int o = 1; o < 32; o <<= 1) {
        int t = __shfl_up_sync(0xffffffffu, inc, o);
        if (lane >= o) inc += t;
    }
    if (lane == 31) wsum[wid] = inc;
    __syncthreads();
    if (wid == 0) {
        int v = wsum[lane];
        int iv = v;
#pragma unroll
        for (int o = 1; o < 32; o <<= 1) {
            int t = __shfl_up_sync(0xffffffffu, iv, o);
            if (lane >= o) iv += t;
        }
        wsum[lane] = iv - v;
    }
    __syncthreads();
    int off = wsum[wid] + (inc - s);
    if (base < Nn) {
        int p[CH];
        int run = off;
#pragma unroll
        for (int c = 0; c < CH; c++) { p[c] = run; run += dv[c]; }
        int4*   rp = (int4*)(g_rowptr + base);
        int4*   cp = (int4*)(g_cursor + base);
        float4* fp = (float4*)(g_dinv + base);
#pragma unroll
        for (int q = 0; q < 5; q++) {
            int4 t; t.x = p[q*4]; t.y = p[q*4+1]; t.z = p[q*4+2]; t.w = p[q*4+3];
            rp[q] = t; cp[q] = t;
            float4 f;
            f.x = rsqrtf((float)dv[q*4+0] + 1.f);
            f.y = rsqrtf((float)dv[q*4+1] + 1.f);
            f.z = rsqrtf((float)dv[q*4+2] + 1.f);
            f.w = rsqrtf((float)dv[q*4+3] + 1.f);
            fp[q] = f;
        }
    }
    if (base == Nn) g_rowptr[Nn] = off;
}

__global__ void place_k(const int* __restrict__ src, const int* __restrict__ dst) {
    int i = blockIdx.x * blockDim.x + threadIdx.x;
    if (i >= Ee) return;
    int s = src[i], d = dst[i];
    int pos = atomicAdd(&g_cursor[d], 1);
    g_csrc[pos] = s;
    g_cw[pos]   = g_dinv[s] * g_dinv[d];
}

// ---------------- split-FP16 GEMM: ldmatrix + cp.async, double-buffered ----------------
// block: 128 rows x 64 cols. grid = (4 colblocks, 157 rowtiles). 8 warps (4m x 2n).
// mode 0: A=xin (+bias) -> g_h ; 1: A=g_h -> g_t ; 2: A=relu(g_t2*sc+sh) -> g_t
__global__ __launch_bounds__(256) void gemm_k(const float* __restrict__ xin,
                                              const float* __restrict__ bias,
                                              int mode, int ktbase, int KT) {
    __shared__ __align__(16) unsigned char sAh[2][4096], sAl[2][4096];
    __shared__ __align__(16) unsigned char sBh[2][2048], sBl[2][2048];

    const int K = (mode == 0) ? XDIM : Hh;
    const float* A = (mode == 0) ? xin : (mode == 1 ? g_h : g_t2);

    const int tid  = threadIdx.x;
    const int lane = tid & 31, wid = tid >> 5;
    const int warp_m = wid & 3, warp_n = wid >> 2;
    const int rowBase = blockIdx.y * 128;
    const int colBase = blockIdx.x * 64;

    // --- staging mapping ---
    const int arow = tid >> 1;           // 0..127
    const int ak8  = tid & 1;            // k8 half
    const int gr   = rowBase + arow;
    const float* aptr = A + (size_t)gr * K + ak8 * 8;
    const uint32_t aoff = tswz(arow, ak8);
    const uint32_t bAh = smem_u32(sAh[0]), bAl = smem_u32(sAl[0]);
    const uint32_t bBh = smem_u32(sBh[0]), bBl = smem_u32(sBl[0]);
    // B cp.async: threads 0-127 -> hi seg tid, 128-255 -> lo seg tid-128
    const int bseg = tid & 127;
    const bool bhi = (tid < 128);

    // --- ldmatrix offsets (within one buffer) ---
    const int lr = lane & 15;
    const uint32_t offA0 = (uint32_t)((warp_m * 32 + lr) * 32 +
                           (((lane >> 4) ^ ((lr >> 2) & 1)) << 4));
    const int bnl = warp_n * 32 + ((lane >> 4) << 3) + (lane & 7);
    const uint32_t offB0 = tswz(bnl, (lane >> 3) & 1);

    float4 acc[2][4];
#pragma unroll
    for (int i = 0; i < 2; i++)
#pragma unroll
        for (int j = 0; j < 4; j++) acc[i][j] = make_float4(0.f, 0.f, 0.f, 0.f);

    float va[8];
    const int q = lane >> 2, t = lane & 3;

    // ---- prologue: stage tile 0 ----
    {
        int tix = (ktbase + 0) * 4 + blockIdx.x;
        const char* gsrc = (const char*)(bhi ? g_Wh16 : g_Wl16) + (size_t)tix * 2048 + bseg * 16;
        uint32_t sdst = (bhi ? bBh : bBl) + bseg * 16;
        CPASYNC16(sdst, gsrc);
        CPCOMMIT();
        float4 v0 = make_float4(0.f,0.f,0.f,0.f), v1 = v0;
        if (gr < Nn) { v0 = *(const float4*)aptr; v1 = *(const float4*)(aptr + 4); }
        va[0]=v0.x; va[1]=v0.y; va[2]=v0.z; va[3]=v0.w;
        va[4]=v1.x; va[5]=v1.y; va[6]=v1.z; va[7]=v1.w;
        if (mode == 2) {
            int kg = ak8 * 8;
#pragma unroll
            for (int c = 0; c < 8; c++)
                va[c] = fmaxf(va[c] * g_scale[kg + c] + g_shift[kg + c], 0.f);
        }
        uint4 H, L;
        uint32_t* hp = (uint32_t*)&H;
        uint32_t* lp = (uint32_t*)&L;
#pragma unroll
        for (int c = 0; c < 4; c++) {
            __half ha = __float2half_rn(va[2*c]),  hb = __float2half_rn(va[2*c+1]);
            float  ra = va[2*c]   - __half2float(ha);
            float  rb = va[2*c+1] - __half2float(hb);
            __half2 hh = __halves2half2(ha, hb);
            __half2 ll = __halves2half2(__float2half_rn(ra), __float2half_rn(rb));
            hp[c] = *(uint32_t*)&hh;
            lp[c] = *(uint32_t*)&ll;
        }
        *(uint4*)(sAh[0] + aoff) = H;
        *(uint4*)(sAl[0] + aoff) = L;
        CPWAIT0();
    }
    __syncthreads();

    for (int kt = 0; kt < KT; kt++) {
        const int cur = kt & 1, nxt = cur ^ 1;
        const bool more = (kt + 1 < KT);
        // ---- start next tile's B (cp.async) and A (regs) ----
        if (more) {
            int tix = (ktbase + kt + 1) * 4 + blockIdx.x;
            const char* gsrc = (const char*)(bhi ? g_Wh16 : g_Wl16) + (size_t)tix * 2048 + bseg * 16;
            uint32_t sdst = (bhi ? bBh : bBl) + nxt * 2048 + bseg * 16;
            CPASYNC16(sdst, gsrc);
            CPCOMMIT();
            float4 v0 = make_float4(0.f,0.f,0.f,0.f), v1 = v0;
            if (gr < Nn) {
                const float* ap = aptr + (kt + 1) * 16;
                v0 = *(const float4*)ap; v1 = *(const float4*)(ap + 4);
            }
            va[0]=v0.x; va[1]=v0.y; va[2]=v0.z; va[3]=v0.w;
            va[4]=v1.x; va[5]=v1.y; va[6]=v1.z; va[7]=v1.w;
            if (mode == 2) {
                int kg = (kt + 1) * 16 + ak8 * 8;
#pragma unroll
                for (int c = 0; c < 8; c++)
                    va[c] = fmaxf(va[c] * g_scale[kg + c] + g_shift[kg + c], 0.f);
            }
        }
        // ---- compute on cur buffer: 8 ldmatrix + 24 mma ----
        {
            uint32_t ah[2][4], al[2][4], bh[2][4], bl[2][4];
            uint32_t aB = cur * 4096, bB = cur * 2048;
            LDSM4(ah[0], bAh + aB + offA0);
            LDSM4(ah[1], bAh + aB + offA0 + 512);
            LDSM4(al[0], bAl + aB + offA0);
            LDSM4(al[1], bAl + aB + offA0 + 512);
            LDSM4(bh[0], bBh + bB + offB0);
            LDSM4(bh[1], bBh + bB + offB0 + 512);
            LDSM4(bl[0], bBl + bB + offB0);
            LDSM4(bl[1], bBl + bB + offB0 + 512);
#pragma unroll
            for (int i = 0; i < 2; i++)
#pragma unroll
                for (int jp = 0; jp < 2; jp++)
#pragma unroll
                    for (int sub = 0; sub < 2; sub++) {
                        int j = jp * 2 + sub;
                        uint32_t b0h = bh[jp][sub*2], b1h = bh[jp][sub*2+1];
                        uint32_t b0l = bl[jp][sub*2], b1l = bl[jp][sub*2+1];
                        mma_f16(acc[i][j], ah[i][0], ah[i][1], ah[i][2], ah[i][3], b0h, b1h);
                        mma_f16(acc[i][j], ah[i][0], ah[i][1], ah[i][2], ah[i][3], b0l, b1l);
                        mma_f16(acc[i][j], al[i][0], al[i][1], al[i][2], al[i][3], b0h, b1h);
                    }
        }
        // ---- finish staging next tile ----
        if (more) {
            uint4 H, L;
            uint32_t* hp = (uint32_t*)&H;
            uint32_t* lp = (uint32_t*)&L;
#pragma unroll
            for (int c = 0; c < 4; c++) {
                __half ha = __float2half_rn(va[2*c]),  hb = __float2half_rn(va[2*c+1]);
                float  ra = va[2*c]   - __half2float(ha);
                float  rb = va[2*c+1] - __half2float(hb);
                __half2 hh = __halves2half2(ha, hb);
                __half2 ll = __halves2half2(__float2half_rn(ra), __float2half_rn(rb));
                hp[c] = *(uint32_t*)&hh;
                lp[c] = *(uint32_t*)&ll;
            }
            *(uint4*)(sAh[nxt] + aoff) = H;
            *(uint4*)(sAl[nxt] + aoff) = L;
            CPWAIT0();
        }
        __syncthreads();
    }

    // ---- epilogue ----
    float* OUT = (mode == 0) ? g_h : g_t;
#pragma unroll
    for (int i = 0; i < 2; i++) {
#pragma unroll
        for (int j = 0; j < 4; j++) {
            int r0 = rowBase + warp_m * 32 + i * 16 + q;
            int c  = colBase + warp_n * 32 + j * 8 + t * 2;
            float bx = 0.f, by = 0.f;
            if (mode == 0) { bx = bias[c]; by = bias[c + 1]; }
            if (r0 < Nn) {
                OUT[(size_t)r0 * Hh + c]     = acc[i][j].x + bx;
                OUT[(size_t)r0 * Hh + c + 1] = acc[i][j].y + by;
            }
            if (r0 + 8 < Nn) {
                OUT[(size_t)(r0 + 8) * Hh + c]     = acc[i][j].z + bx;
                OUT[(size_t)(r0 + 8) * Hh + c + 1] = acc[i][j].w + by;
            }
        }
    }
}

// ---------------- aggregate + fused BN stats ----------------
__global__ __launch_bounds__(256) void agg_k(const float* __restrict__ convBi) {
    __shared__ float s_sum[Hh], s_sq[Hh];
    int tid = threadIdx.x, lane = tid & 31;
    s_sum[tid] = 0.f; s_sq[tid] = 0.f;
    __syncthreads();

    int w = blockIdx.x * 8 + (tid >> 5);
    int beg = g_rowptr[w], end = g_rowptr[w + 1];
    float4 a0 = make_float4(0.f, 0.f, 0.f, 0.f), a1 = a0;
    const float4* T = (const float4*)g_t;
    for (int e = beg; e < end; e++) {
        int   s  = g_csrc[e];
        float wt = g_cw[e];
        float4 v0 = T[s * 64 + lane];
        float4 v1 = T[s * 64 + lane + 32];
        a0.x += v0.x * wt; a0.y += v0.y * wt; a0.z += v0.z * wt; a0.w += v0.w * wt;
        a1.x += v1.x * wt; a1.y += v1.y * wt; a1.z += v1.z * wt; a1.w += v1.w * wt;
    }
    float sn = g_dinv[w]; sn *= sn;
    float4 t0 = T[w * 64 + lane], t1 = T[w * 64 + lane + 32];
    const float4* B4 = (const float4*)convBi;
    float4 b0 = B4[lane], b1 = B4[lane + 32];
    a0.x += t0.x * sn + b0.x; a0.y += t0.y * sn + b0.y;
    a0.z += t0.z * sn + b0.z; a0.w += t0.w * sn + b0.w;
    a1.x += t1.x * sn + b1.x; a1.y += t1.y * sn + b1.y;
    a1.z += t1.z * sn + b1.z; a1.w += t1.w * sn + b1.w;
    ((float4*)g_t2)[w * 64 + lane]      = a0;
    ((float4*)g_t2)[w * 64 + lane + 32] = a1;

    int c0 = lane * 4, c1 = 128 + lane * 4;
    atomicAdd(&s_sum[c0+0], a0.x); atomicAdd(&s_sum[c0+1], a0.y);
    atomicAdd(&s_sum[c0+2], a0.z); atomicAdd(&s_sum[c0+3], a0.w);
    atomicAdd(&s_sum[c1+0], a1.x); atomicAdd(&s_sum[c1+1], a1.y);
    atomicAdd(&s_sum[c1+2], a1.z); atomicAdd(&s_sum[c1+3], a1.w);
    atomicAdd(&s_sq[c0+0], a0.x*a0.x); atomicAdd(&s_sq[c0+1], a0.y*a0.y);
    atomicAdd(&s_sq[c0+2], a0.z*a0.z); atomicAdd(&s_sq[c0+3], a0.w*a0.w);
    atomicAdd(&s_sq[c1+0], a1.x*a1.x); atomicAdd(&s_sq[c1+1], a1.y*a1.y);
    atomicAdd(&s_sq[c1+2], a1.z*a1.z); atomicAdd(&s_sq[c1+3], a1.w*a1.w);
    __syncthreads();
    atomicAdd(&g_colsum[tid], s_sum[tid]);
    atomicAdd(&g_colsq[tid],  s_sq[tid]);
}

__global__ void bnprep_k(const float* __restrict__ gamma, const float* __restrict__ beta) {
    int j = threadIdx.x;
    const float invN = 1.f / (float)Nn;
    float m  = g_colsum[j] * invN;
    float v  = g_colsq[j] * invN - m * m;
    float rs = rsqrtf(v + EPSF);
    float sc = gamma[j] * rs;
    g_scale[j] = sc;
    g_shift[j] = beta[j] - m * sc;
    g_colsum[j] = 0.f;
    g_colsq[j]  = 0.f;
}

// ---------------- global mean pool with fused final BN+ReLU ----------------
__global__ void pool_k(const int* __restrict__ batch) {
    int j  = threadIdx.x;
    int r0 = blockIdx.x * 80;
    float sc = g_scale[j], sh = g_shift[j];
    int cur = -1;
    float acc = 0.f;
    for (int r = 0; r < 80; r++) {
        int n = r0 + r;
        if (n >= Nn) break;
        int b = batch[n];
        if (b != cur) {
            if (cur >= 0) atomicAdd(&g_gsum[cur * Hh + j], acc);
            cur = b; acc = 0.f;
        }
        acc += fmaxf(g_t2[(size_t)n * Hh + j] * sc + sh, 0.f);
    }
    if (cur >= 0) atomicAdd(&g_gsum[cur * Hh + j], acc);
}

// ---------------- MLP head ----------------
__global__ void mlp1_k(const float* __restrict__ W, const float* __restrict__ b) {
    __shared__ float s[Hh];
    int tid = threadIdx.x;
    int g   = blockIdx.x;
    float inv = 1.f / fmaxf((float)g_gcnt[g], 1.f);
    s[tid] = g_gsum[g * Hh + tid] * inv;
    __syncthreads();
    float sum = b[tid];
#pragma unroll 8
    for (int k = 0; k < Hh; k++) sum += s[k] * W[k * Hh + tid];
    g_m1[g * Hh + tid] = sum;
}

__global__ void mlp2_k(const float* __restrict__ gamma, const float* __restrict__ beta,
                       const float* __restrict__ W, const float* __restrict__ b) {
    __shared__ float s[Hh];
    int tid = threadIdx.x;
    int g   = blockIdx.x;
    float su = 0.f, q = 0.f;
    for (int r = 0; r < GG; r++) { float v = g_m1[r * Hh + tid]; su += v; q += v * v; }
    float m   = su * (1.f / GG);
    float var = q * (1.f / GG) - m * m;
    float sc  = gamma[tid] * rsqrtf(var + EPSF);
    float sh  = beta[tid] - m * sc;
    s[tid] = fmaxf(g_m1[g * Hh + tid] * sc + sh, 0.f);
    __syncthreads();
    float sum = b[tid];
#pragma unroll 8
    for (int k = 0; k < Hh; k++) sum += s[k] * W[k * Hh + tid];
    g_m2[g * Hh + tid] = sum;
}

__global__ void final_k(const float* __restrict__ gamma, const float* __restrict__ beta,
                        const float* __restrict__ W3, const float* __restrict__ b3,
                        float* __restrict__ out) {
    __shared__ float s[Hh];
    int tid = threadIdx.x;
    int g   = blockIdx.x;
    float su = 0.f, q = 0.f;
    for (int r = 0; r < GG; r++) { float v = g_m2[r * Hh + tid]; su += v; q += v * v; }
    float m   = su * (1.f / GG);
    float var = q * (1.f / GG) - m * m;
    float sc  = gamma[tid] * rsqrtf(var + EPSF);
    float sh  = beta[tid] - m * sc;
    s[tid] = g_m2[g * Hh + tid] * sc + sh;
    __syncthreads();
    if (tid < CC) {
        float sum = b3[tid];
        for (int k = 0; k < Hh; k++) sum += s[k] * W3[k * CC + tid];
        out[g * CC + tid] = sum;
    }
}

// ---------------- launch ----------------
extern "C" void kernel_launch(void* const* d_in, const int* in_sizes, int n_in,
                              void* d_out, int out_size) {
    const float* x     = (const float*)d_in[0];
    const int*   ei    = (const int*)  d_in[1];
    const int*   batch = (const int*)  d_in[2];
    const float* encW  = (const float*)d_in[3];
    const float* encB  = (const float*)d_in[4];
    const float* convW = (const float*)d_in[5];
    const float* convB = (const float*)d_in[6];
    const float* bnG   = (const float*)d_in[7];
    const float* bnB   = (const float*)d_in[8];
    const float* fcW1  = (const float*)d_in[9];
    const float* fcB1  = (const float*)d_in[10];
    const float* fcG1  = (const float*)d_in[11];
    const float* fcBe1 = (const float*)d_in[12];
    const float* fcW2  = (const float*)d_in[13];
    const float* fcB2  = (const float*)d_in[14];
    const float* fcG2  = (const float*)d_in[15];
    const float* fcBe2 = (const float*)d_in[16];
    const float* fcW3  = (const float*)d_in[17];
    const float* fcB3  = (const float*)d_in[18];
    const int* srcp = ei;
    const int* dstp = ei + Ee;
    float* out = (float*)d_out;

    dim3 gg(4, (Nn + 127) / 128);     // 4 colblocks x 157 rowtiles

    zero_k<<<(GG * Hh + 255) / 256, 256>>>();
    prep_k<<<((XDIM + LL * Hh) * Hh + 255) / 256, 256>>>(encW, convW);
    gemm_k<<<gg, 256>>>(x, encB, 0, 0, 8);                     // enc -> g_h
    gemm_k<<<gg, 256>>>(nullptr, nullptr, 1, 8, 16);           // conv0 [capture slot 4]

    degree_k<<<(Ee + 255) / 256, 256>>>(dstp, batch);
    scan_k  <<<1, 1024>>>();
    place_k <<<(Ee + 255) / 256, 256>>>(srcp, dstp);

    agg_k   <<<Nn / 8, 256>>>(convB);
    bnprep_k<<<1, 256>>>(bnG, bnB);
    for (int l = 1; l < LL; l++) {
        gemm_k  <<<gg, 256>>>(nullptr, nullptr, 2, 8 + l * 16, 16);
        agg_k   <<<Nn / 8, 256>>>(convB + l * Hh);
        bnprep_k<<<1, 256>>>(bnG + l * Hh, bnB + l * Hh);
    }

    pool_k <<<250, 256>>>(batch);
    mlp1_k <<<GG, 256>>>(fcW1, fcB1);
    mlp2_k <<<GG, 256>>>(fcG1, fcBe1, fcW2, fcB2);
    final_k<<<GG, 256>>>(fcG2, fcBe2, fcW3, fcB3, out);
}